// round 7
// baseline (speedup 1.0000x reference)
#include <cuda_runtime.h>
#include <cuda_bf16.h>
#include <cstdint>

#define N 4096
#define FIN 512
#define FOUT 256
#define ALPHA 0.2f
#define JSPLIT 2
#define KCTA (N / JSPLIT)   // 2048
#define NCHUNK (KCTA / 64)  // 32

// ---------------- device scratch ----------------
__device__ float g_wh[N * FOUT];
__device__ float g_fsrc[N];
__device__ float g_fdst[N];
__device__ float g_mi[N];
__device__ float g_rz[N];
__device__ unsigned g_mask[N * (N / 32)];                    // 2 MB
__device__ __align__(16) __nv_bfloat16 g_wh_hi[N * FOUT];    // 2 MB [j][d]
__device__ __align__(16) __nv_bfloat16 g_wh_lo[N * FOUT];    // 2 MB
__device__ __align__(16) float g_part[(size_t)JSPLIT * N * FOUT];  // 8 MB

// ---------------- base-ISA PTX helpers ----------------
__device__ __forceinline__ uint32_t smem_u32(const void* p) {
    uint32_t a;
    asm("{ .reg .u64 t; cvta.to.shared.u64 t, %1; cvt.u32.u64 %0, t; }" : "=r"(a) : "l"(p));
    return a;
}
__device__ __forceinline__ void ldm_x4(uint32_t* r, uint32_t addr) {
    asm volatile("ldmatrix.sync.aligned.m8n8.x4.shared.b16 {%0,%1,%2,%3}, [%4];"
                 : "=r"(r[0]), "=r"(r[1]), "=r"(r[2]), "=r"(r[3]) : "r"(addr));
}
__device__ __forceinline__ void ldm_x4_t(uint32_t* r, uint32_t addr) {
    asm volatile("ldmatrix.sync.aligned.m8n8.x4.trans.shared.b16 {%0,%1,%2,%3}, [%4];"
                 : "=r"(r[0]), "=r"(r[1]), "=r"(r[2]), "=r"(r[3]) : "r"(addr));
}
__device__ __forceinline__ void mma_bf16(float* c, const uint32_t* a, const uint32_t* b) {
    asm volatile(
        "mma.sync.aligned.m16n8k16.row.col.f32.bf16.bf16.f32 "
        "{%0,%1,%2,%3}, {%4,%5,%6,%7}, {%8,%9}, {%0,%1,%2,%3};"
        : "+f"(c[0]), "+f"(c[1]), "+f"(c[2]), "+f"(c[3])
        : "r"(a[0]), "r"(a[1]), "r"(a[2]), "r"(a[3]), "r"(b[0]), "r"(b[1]));
}
#define CP_ASYNC16(dst, src) \
    asm volatile("cp.async.cg.shared.global [%0], [%1], 16;" :: "r"(dst), "l"(src))
#define CP_COMMIT() asm volatile("cp.async.commit_group;" ::: "memory")
#define CP_WAIT0() asm volatile("cp.async.wait_group 0;" ::: "memory")

// ---------------- f32x2 helpers ----------------
__device__ __forceinline__ unsigned long long pk(float lo, float hi) {
    unsigned long long r;
    asm("mov.b64 %0, {%1,%2};" : "=l"(r) : "f"(lo), "f"(hi));
    return r;
}
__device__ __forceinline__ unsigned long long f2fma(unsigned long long a,
                                                    unsigned long long b,
                                                    unsigned long long c) {
    unsigned long long d;
    asm("fma.rn.f32x2 %0, %1, %2, %3;" : "=l"(d) : "l"(a), "l"(b), "l"(c));
    return d;
}
__device__ __forceinline__ float lof(unsigned long long v) { return __uint_as_float((unsigned)v); }
__device__ __forceinline__ float hif(unsigned long long v) { return __uint_as_float((unsigned)(v >> 32)); }

// ---------------- kernel 1: wh = h @ W + b, plus bf16 hi/lo split ------------
__global__ __launch_bounds__(256) void k_gemm_wh(const float* __restrict__ h,
                                                 const float* __restrict__ Wm,
                                                 const float* __restrict__ bias) {
    __shared__ float As[64][33];
    __shared__ float Bs[32][64];
    const int t = threadIdx.x;
    const int m0 = blockIdx.x * 64, n0 = blockIdx.y * 64;
    const int tx = t & 15, ty = t >> 4;
    unsigned long long acc2[4][2];
#pragma unroll
    for (int i = 0; i < 4; i++) { acc2[i][0] = 0ull; acc2[i][1] = 0ull; }
    for (int k0 = 0; k0 < FIN; k0 += 32) {
#pragma unroll
        for (int u = 0; u < 2; u++) {
            int idx = t + u * 256, r = idx >> 3, c = (idx & 7) * 4;
            float4 v = *(const float4*)(h + (size_t)(m0 + r) * FIN + k0 + c);
            As[r][c] = v.x; As[r][c + 1] = v.y; As[r][c + 2] = v.z; As[r][c + 3] = v.w;
        }
#pragma unroll
        for (int u = 0; u < 2; u++) {
            int idx = t + u * 256, r = idx >> 4, c = (idx & 15) * 4;
            *(float4*)(&Bs[r][c]) = *(const float4*)(Wm + (size_t)(k0 + r) * FOUT + n0 + c);
        }
        __syncthreads();
#pragma unroll
        for (int k = 0; k < 32; k++) {
            double2 bd = *(const double2*)(&Bs[k][tx * 4]);
            unsigned long long b01 = __double_as_longlong(bd.x);
            unsigned long long b23 = __double_as_longlong(bd.y);
#pragma unroll
            for (int i = 0; i < 4; i++) {
                float a = As[ty * 4 + i][k];
                unsigned long long ap = pk(a, a);
                acc2[i][0] = f2fma(ap, b01, acc2[i][0]);
                acc2[i][1] = f2fma(ap, b23, acc2[i][1]);
            }
        }
        __syncthreads();
    }
    const int n = n0 + tx * 4;
    float4 bv = *(const float4*)(bias + n);
#pragma unroll
    for (int i = 0; i < 4; i++) {
        float4 o;
        o.x = lof(acc2[i][0]) + bv.x; o.y = hif(acc2[i][0]) + bv.y;
        o.z = lof(acc2[i][1]) + bv.z; o.w = hif(acc2[i][1]) + bv.w;
        size_t gi = (size_t)(m0 + ty * 4 + i) * FOUT + n;
        *(float4*)(g_wh + gi) = o;
        __nv_bfloat162 ha = __floats2bfloat162_rn(o.x, o.y);
        __nv_bfloat162 hb = __floats2bfloat162_rn(o.z, o.w);
        __nv_bfloat162 la = __floats2bfloat162_rn(o.x - __bfloat162float(ha.x),
                                                  o.y - __bfloat162float(ha.y));
        __nv_bfloat162 lb = __floats2bfloat162_rn(o.z - __bfloat162float(hb.x),
                                                  o.w - __bfloat162float(hb.y));
        *(uint2*)(g_wh_hi + gi) = make_uint2(*(unsigned*)&ha, *(unsigned*)&hb);
        *(uint2*)(g_wh_lo + gi) = make_uint2(*(unsigned*)&la, *(unsigned*)&lb);
    }
}

// ---------------- kernel 2: f_src / f_dst ----------------
__global__ __launch_bounds__(256) void k_fsd(const float* __restrict__ a1,
                                             const float* __restrict__ a2,
                                             const float* __restrict__ ab) {
    const int warp = threadIdx.x >> 5, lane = threadIdx.x & 31;
    const int i = blockIdx.x * 8 + warp;
    const float4* row = (const float4*)(g_wh + (size_t)i * FOUT);
    const float4* A1 = (const float4*)a1;
    const float4* A2 = (const float4*)a2;
    float s1 = 0.f, s2 = 0.f;
#pragma unroll
    for (int u = 0; u < 2; u++) {
        float4 v = row[lane + u * 32], x = A1[lane + u * 32], y = A2[lane + u * 32];
        s1 += v.x * x.x + v.y * x.y + v.z * x.z + v.w * x.w;
        s2 += v.x * y.x + v.y * y.y + v.z * y.z + v.w * y.w;
    }
#pragma unroll
    for (int o = 16; o; o >>= 1) {
        s1 += __shfl_down_sync(0xffffffffu, s1, o);
        s2 += __shfl_down_sync(0xffffffffu, s2, o);
    }
    if (lane == 0) { g_fsrc[i] = s1 + ab[0]; g_fdst[i] = s2; }
}

// ---------------- kernel 3: softmax stats + bit-pack (256 thr, int4) --------
__global__ __launch_bounds__(256) void k_prep(const int* __restrict__ adj) {
    const int i = blockIdx.x, t = threadIdx.x;
    const float fs = g_fsrc[i];
    const int4* arow = (const int4*)(adj + (size_t)i * N);

    float fdv[16];
    const float4* fdp = (const float4*)g_fdst;
#pragma unroll
    for (int v = 0; v < 4; v++) {
        float4 f = fdp[t * 4 + v];
        fdv[v * 4 + 0] = f.x; fdv[v * 4 + 1] = f.y;
        fdv[v * 4 + 2] = f.z; fdv[v * 4 + 3] = f.w;
    }
    unsigned bits = 0;
#pragma unroll
    for (int q = 0; q < 4; q++) {
        int4 a = arow[t * 4 + q];
        if (a.x > 0) bits |= 1u << (q * 4 + 0);
        if (a.y > 0) bits |= 1u << (q * 4 + 1);
        if (a.z > 0) bits |= 1u << (q * 4 + 2);
        if (a.w > 0) bits |= 1u << (q * 4 + 3);
    }
    unsigned other = __shfl_xor_sync(0xffffffffu, bits, 1);
    if ((t & 1) == 0) g_mask[(size_t)i * 128 + (t >> 1)] = bits | (other << 16);

    float mx = -3.4e38f;
#pragma unroll
    for (int v = 0; v < 16; v++)
        if ((bits >> v) & 1u) mx = fmaxf(mx, fdv[v]);
#pragma unroll
    for (int o = 16; o; o >>= 1) mx = fmaxf(mx, __shfl_xor_sync(0xffffffffu, mx, o));
    __shared__ float redm[8];
    __shared__ float reds[8];
    if ((t & 31) == 0) redm[t >> 5] = mx;
    __syncthreads();
    float mxall = redm[0];
#pragma unroll
    for (int w = 1; w < 8; w++) mxall = fmaxf(mxall, redm[w]);
    float xm = fs + mxall;
    float mi = fmaxf(xm, ALPHA * xm);

    float s = 0.f;
#pragma unroll
    for (int v = 0; v < 16; v++)
        if ((bits >> v) & 1u) {
            float x = fs + fdv[v];
            s += __expf(fmaxf(x, ALPHA * x) - mi);
        }
#pragma unroll
    for (int o = 16; o; o >>= 1) s += __shfl_xor_sync(0xffffffffu, s, o);
    if ((t & 31) == 0) reds[t >> 5] = s;
    __syncthreads();
    if (t == 0) {
        float stot = 0.f;
#pragma unroll
        for (int w = 0; w < 8; w++) stot += reds[w];
        g_mi[i] = mi;
        g_rz[i] = (stot > 0.f) ? (1.f / stot) : 0.f;
    }
}

// ---------------- kernel 4: HMMA attention GEMM, 1024 threads / 32 warps ----
// warp grid: mw = warp>>3 (four 16-row quarters), nw = warp&7 (eight 32-col slices)
#define SM_FD 0
#define SM_MASK 8192
#define SM_STG0 24576
#define A_HI 0
#define A_LO 9216
#define B_HI 18432
#define B_LO 52224
#define STG 86016
#define SMEM_AT (SM_STG0 + 2 * STG)  // 196608

__global__ __launch_bounds__(1024, 1) void k_attn_h() {
    extern __shared__ char smem[];
    const uint32_t sbase = smem_u32(smem);
    float* fd_s = (float*)(smem + SM_FD);
    unsigned* mask_s = (unsigned*)(smem + SM_MASK);
    const int t = threadIdx.x;
    const int lane = t & 31, warp = t >> 5;
    const int mw = warp >> 3, nw = warp & 7;
    const int i0 = blockIdx.x * 64;
    const int js = blockIdx.y;
    const int jorg = js * KCTA;

    // per-thread A-gen constants: thread generates weights for row i = t>>4
    const int gi = i0 + (t >> 4);
    const float fsi = g_fsrc[gi];
    const float mii = g_mi[gi];
    const float rzi = g_rz[gi];

    // preload fd (2048 floats) + mask (64 rows x 64 words = 4096)
    if (t < 512) *(float4*)(fd_s + t * 4) = *(const float4*)(g_fdst + jorg + t * 4);
#pragma unroll
    for (int u = 0; u < 4; u++) {
        int idx = t + 1024 * u;
        mask_s[idx] = g_mask[(size_t)(i0 + (idx >> 6)) * 128 + js * 64 + (idx & 63)];
    }
    __syncthreads();

    auto fill_B = [&](int c2, uint32_t stg_s) {
        size_t jg = (size_t)jorg + (size_t)c2 * 64;
#pragma unroll
        for (int u = 0; u < 2; u++) {
            int idx = t + 1024 * u;
            int j = idx >> 5, dq = idx & 31;
            uint32_t dst = stg_s + B_HI + j * 528 + dq * 16;
            size_t src = (jg + j) * FOUT + dq * 8;
            CP_ASYNC16(dst, (const void*)(g_wh_hi + src));
            CP_ASYNC16(dst + (B_LO - B_HI), (const void*)(g_wh_lo + src));
        }
    };
    // each thread: row t>>4 (0..63), j-quad t&15 (4 j values)
    auto fill_A = [&](int c2, char* stgp) {
        const int row = t >> 4, quad = t & 15;
        unsigned w = mask_s[row * 64 + c2 * 2 + (quad >> 3)] >> ((quad & 7) * 4);
        const float* fdp = fd_s + c2 * 64 + quad * 4;
        uint32_t hv[2], lv[2];
#pragma unroll
        for (int v = 0; v < 4; v += 2) {
            float e0 = 0.f, e1 = 0.f;
            if ((w >> v) & 1u) {
                float x = fsi + fdp[v];
                e0 = __expf(fmaxf(x, ALPHA * x) - mii) * rzi;
            }
            if ((w >> (v + 1)) & 1u) {
                float x = fsi + fdp[v + 1];
                e1 = __expf(fmaxf(x, ALPHA * x) - mii) * rzi;
            }
            __nv_bfloat162 h2 = __floats2bfloat162_rn(e0, e1);
            __nv_bfloat162 l2 = __floats2bfloat162_rn(e0 - __bfloat162float(h2.x),
                                                      e1 - __bfloat162float(h2.y));
            hv[v >> 1] = *(uint32_t*)&h2;
            lv[v >> 1] = *(uint32_t*)&l2;
        }
        char* pA = stgp + row * 144 + quad * 8;
        *(uint2*)(pA + A_HI) = make_uint2(hv[0], hv[1]);
        *(uint2*)(pA + A_LO) = make_uint2(lv[0], lv[1]);
    };

    float acc[4][4];
#pragma unroll
    for (int b = 0; b < 4; b++)
#pragma unroll
        for (int c = 0; c < 4; c++) acc[b][c] = 0.f;

    // ldmatrix per-thread base offsets
    const uint32_t a_off = (mw * 16 + (lane & 15)) * 144 + (lane >> 4) * 16;
    const uint32_t b_off = (lane & 15) * 528 + (nw * 32 + (lane >> 4) * 8) * 2;

    // prolog: fill chunk 0 into stage 0
    fill_B(0, sbase + SM_STG0);
    CP_COMMIT();
    fill_A(0, smem + SM_STG0);
    CP_WAIT0();
    __syncthreads();

#pragma unroll 1
    for (int c = 0; c < NCHUNK; c++) {
        const int s = c & 1;
        const uint32_t stg = SM_STG0 + (uint32_t)s * STG;
        const uint32_t stg2 = SM_STG0 + (uint32_t)(s ^ 1) * STG;
        const uint32_t Ah = sbase + stg + A_HI;
        const uint32_t Al = sbase + stg + A_LO;
        const uint32_t Bh = sbase + stg + B_HI;
        const uint32_t Bl = sbase + stg + B_LO;

        if (c + 1 < NCHUNK) { fill_B(c + 1, sbase + stg2); CP_COMMIT(); }

#pragma unroll
        for (int kk = 0; kk < 4; kk++) {
            uint32_t ah[4], al[4], bh[2][4], bl[2][4];
            const uint32_t ao = a_off + kk * 32;
            const uint32_t bo = b_off + kk * 8448;
            ldm_x4(ah, Ah + ao);
            ldm_x4(al, Al + ao);
#pragma unroll
            for (int seg = 0; seg < 2; seg++) {
                ldm_x4_t(bh[seg], Bh + bo + seg * 32);
                ldm_x4_t(bl[seg], Bl + bo + seg * 32);
            }
#pragma unroll
            for (int nb = 0; nb < 4; nb++) {
                const uint32_t* bfh = &bh[nb >> 1][(nb & 1) * 2];
                const uint32_t* bfl = &bl[nb >> 1][(nb & 1) * 2];
                mma_bf16(acc[nb], ah, bfh);  // hi*hi
                mma_bf16(acc[nb], ah, bfl);  // hi*lo
                mma_bf16(acc[nb], al, bfh);  // lo*hi
            }
            if (kk == 0 && c + 1 < NCHUNK) fill_A(c + 1, smem + stg2);
        }

        CP_WAIT0();
        __syncthreads();
    }

    // epilogue: write partials
    float* base = g_part + (size_t)js * ((size_t)N * FOUT);
    {
        int ir = i0 + mw * 16 + (lane >> 2);
#pragma unroll
        for (int nb = 0; nb < 4; nb++) {
            int d = nw * 32 + nb * 8 + (lane & 3) * 2;
            *(float2*)(base + (size_t)ir * FOUT + d) =
                make_float2(acc[nb][0], acc[nb][1]);
            *(float2*)(base + (size_t)(ir + 8) * FOUT + d) =
                make_float2(acc[nb][2], acc[nb][3]);
        }
    }
}

// ---------------- kernel 5: combine partials + elu ----------------
__global__ __launch_bounds__(256) void k_comb(float* __restrict__ out) {
    const size_t idx = ((size_t)blockIdx.x * 256 + threadIdx.x) * 4;
    const size_t stride = (size_t)N * FOUT;
    float4 a = *(const float4*)(g_part + idx);
    float4 b = *(const float4*)(g_part + stride + idx);
    float4 o;
    o.x = a.x + b.x; o.y = a.y + b.y; o.z = a.z + b.z; o.w = a.w + b.w;
    o.x = o.x > 0.f ? o.x : (__expf(o.x) - 1.f);
    o.y = o.y > 0.f ? o.y : (__expf(o.y) - 1.f);
    o.z = o.z > 0.f ? o.z : (__expf(o.z) - 1.f);
    o.w = o.w > 0.f ? o.w : (__expf(o.w) - 1.f);
    *(float4*)(out + idx) = o;
}

// ---------------- launch ----------------
extern "C" void kernel_launch(void* const* d_in, const int* in_sizes, int n_in,
                              void* d_out, int out_size) {
    const int* adj = (const int*)d_in[0];
    const float* h = (const float*)d_in[1];
    const float* Wm = (const float*)d_in[2];
    const float* b = (const float*)d_in[3];
    const float* a1 = (const float*)d_in[4];
    const float* a2 = (const float*)d_in[5];
    const float* ab = (const float*)d_in[6];
    float* out = (float*)d_out;

    static bool attr_set = false;
    if (!attr_set) {
        cudaFuncSetAttribute(k_attn_h, cudaFuncAttributeMaxDynamicSharedMemorySize, SMEM_AT);
        attr_set = true;
    }

    k_gemm_wh<<<dim3(N / 64, FOUT / 64), 256>>>(h, Wm, b);
    k_fsd<<<N / 8, 256>>>(a1, a2, ab);
    k_prep<<<N, 256>>>(adj);
    k_attn_h<<<dim3(N / 64, JSPLIT), 1024, SMEM_AT>>>();
    k_comb<<<(N * FOUT) / 1024, 256>>>(out);
}

// round 8
// speedup vs baseline: 1.1119x; 1.1119x over previous
#include <cuda_runtime.h>
#include <cuda_bf16.h>
#include <cuda_fp16.h>
#include <cstdint>

#define N 4096
#define FIN 512
#define FOUT 256
#define ALPHA 0.2f
#define JSPLIT 2
#define KCTA (N / JSPLIT)   // 2048
#define NCHUNK (KCTA / 64)  // 32

// ---------------- device scratch ----------------
__device__ float g_wh[N * FOUT];
__device__ float g_fsrc[N];
__device__ float g_fdst[N];
__device__ float g_mi[N];
__device__ float g_rz[N];
__device__ unsigned g_mask[N * (N / 32)];                    // 2 MB
__device__ __align__(16) __half g_wh_hi[N * FOUT];           // 2 MB [j][d] fp16 hi
__device__ __align__(16) __half g_wh_lo[N * FOUT];           // 2 MB fp16 lo (residual)
__device__ __align__(16) float g_part[(size_t)JSPLIT * N * FOUT];  // 8 MB

// ---------------- base-ISA PTX helpers ----------------
__device__ __forceinline__ uint32_t smem_u32(const void* p) {
    uint32_t a;
    asm("{ .reg .u64 t; cvta.to.shared.u64 t, %1; cvt.u32.u64 %0, t; }" : "=r"(a) : "l"(p));
    return a;
}
__device__ __forceinline__ void ldm_x4(uint32_t* r, uint32_t addr) {
    asm volatile("ldmatrix.sync.aligned.m8n8.x4.shared.b16 {%0,%1,%2,%3}, [%4];"
                 : "=r"(r[0]), "=r"(r[1]), "=r"(r[2]), "=r"(r[3]) : "r"(addr));
}
__device__ __forceinline__ void ldm_x4_t(uint32_t* r, uint32_t addr) {
    asm volatile("ldmatrix.sync.aligned.m8n8.x4.trans.shared.b16 {%0,%1,%2,%3}, [%4];"
                 : "=r"(r[0]), "=r"(r[1]), "=r"(r[2]), "=r"(r[3]) : "r"(addr));
}
__device__ __forceinline__ void mma_f16(float* c, const uint32_t* a, const uint32_t* b) {
    asm volatile(
        "mma.sync.aligned.m16n8k16.row.col.f32.f16.f16.f32 "
        "{%0,%1,%2,%3}, {%4,%5,%6,%7}, {%8,%9}, {%0,%1,%2,%3};"
        : "+f"(c[0]), "+f"(c[1]), "+f"(c[2]), "+f"(c[3])
        : "r"(a[0]), "r"(a[1]), "r"(a[2]), "r"(a[3]), "r"(b[0]), "r"(b[1]));
}
#define CP_ASYNC16(dst, src) \
    asm volatile("cp.async.cg.shared.global [%0], [%1], 16;" :: "r"(dst), "l"(src))
#define CP_COMMIT() asm volatile("cp.async.commit_group;" ::: "memory")
#define CP_WAIT0() asm volatile("cp.async.wait_group 0;" ::: "memory")

// ---------------- f32x2 helpers ----------------
__device__ __forceinline__ unsigned long long pk(float lo, float hi) {
    unsigned long long r;
    asm("mov.b64 %0, {%1,%2};" : "=l"(r) : "f"(lo), "f"(hi));
    return r;
}
__device__ __forceinline__ unsigned long long f2fma(unsigned long long a,
                                                    unsigned long long b,
                                                    unsigned long long c) {
    unsigned long long d;
    asm("fma.rn.f32x2 %0, %1, %2, %3;" : "=l"(d) : "l"(a), "l"(b), "l"(c));
    return d;
}
__device__ __forceinline__ float lof(unsigned long long v) { return __uint_as_float((unsigned)v); }
__device__ __forceinline__ float hif(unsigned long long v) { return __uint_as_float((unsigned)(v >> 32)); }

// ---------------- kernel 1: wh = h @ W + b, plus fp16 hi/lo split -----------
__global__ __launch_bounds__(256) void k_gemm_wh(const float* __restrict__ h,
                                                 const float* __restrict__ Wm,
                                                 const float* __restrict__ bias) {
    __shared__ float As[64][33];
    __shared__ float Bs[32][64];
    const int t = threadIdx.x;
    const int m0 = blockIdx.x * 64, n0 = blockIdx.y * 64;
    const int tx = t & 15, ty = t >> 4;
    unsigned long long acc2[4][2];
#pragma unroll
    for (int i = 0; i < 4; i++) { acc2[i][0] = 0ull; acc2[i][1] = 0ull; }
    for (int k0 = 0; k0 < FIN; k0 += 32) {
#pragma unroll
        for (int u = 0; u < 2; u++) {
            int idx = t + u * 256, r = idx >> 3, c = (idx & 7) * 4;
            float4 v = *(const float4*)(h + (size_t)(m0 + r) * FIN + k0 + c);
            As[r][c] = v.x; As[r][c + 1] = v.y; As[r][c + 2] = v.z; As[r][c + 3] = v.w;
        }
#pragma unroll
        for (int u = 0; u < 2; u++) {
            int idx = t + u * 256, r = idx >> 4, c = (idx & 15) * 4;
            *(float4*)(&Bs[r][c]) = *(const float4*)(Wm + (size_t)(k0 + r) * FOUT + n0 + c);
        }
        __syncthreads();
#pragma unroll
        for (int k = 0; k < 32; k++) {
            double2 bd = *(const double2*)(&Bs[k][tx * 4]);
            unsigned long long b01 = __double_as_longlong(bd.x);
            unsigned long long b23 = __double_as_longlong(bd.y);
#pragma unroll
            for (int i = 0; i < 4; i++) {
                float a = As[ty * 4 + i][k];
                unsigned long long ap = pk(a, a);
                acc2[i][0] = f2fma(ap, b01, acc2[i][0]);
                acc2[i][1] = f2fma(ap, b23, acc2[i][1]);
            }
        }
        __syncthreads();
    }
    const int n = n0 + tx * 4;
    float4 bv = *(const float4*)(bias + n);
#pragma unroll
    for (int i = 0; i < 4; i++) {
        float4 o;
        o.x = lof(acc2[i][0]) + bv.x; o.y = hif(acc2[i][0]) + bv.y;
        o.z = lof(acc2[i][1]) + bv.z; o.w = hif(acc2[i][1]) + bv.w;
        size_t gi = (size_t)(m0 + ty * 4 + i) * FOUT + n;
        *(float4*)(g_wh + gi) = o;
        __half2 ha = __floats2half2_rn(o.x, o.y);
        __half2 hb = __floats2half2_rn(o.z, o.w);
        __half2 la = __floats2half2_rn(o.x - __half2float(ha.x),
                                       o.y - __half2float(ha.y));
        __half2 lb = __floats2half2_rn(o.z - __half2float(hb.x),
                                       o.w - __half2float(hb.y));
        *(uint2*)(g_wh_hi + gi) = make_uint2(*(unsigned*)&ha, *(unsigned*)&hb);
        *(uint2*)(g_wh_lo + gi) = make_uint2(*(unsigned*)&la, *(unsigned*)&lb);
    }
}

// ---------------- kernel 2: f_src / f_dst ----------------
__global__ __launch_bounds__(256) void k_fsd(const float* __restrict__ a1,
                                             const float* __restrict__ a2,
                                             const float* __restrict__ ab) {
    const int warp = threadIdx.x >> 5, lane = threadIdx.x & 31;
    const int i = blockIdx.x * 8 + warp;
    const float4* row = (const float4*)(g_wh + (size_t)i * FOUT);
    const float4* A1 = (const float4*)a1;
    const float4* A2 = (const float4*)a2;
    float s1 = 0.f, s2 = 0.f;
#pragma unroll
    for (int u = 0; u < 2; u++) {
        float4 v = row[lane + u * 32], x = A1[lane + u * 32], y = A2[lane + u * 32];
        s1 += v.x * x.x + v.y * x.y + v.z * x.z + v.w * x.w;
        s2 += v.x * y.x + v.y * y.y + v.z * y.z + v.w * y.w;
    }
#pragma unroll
    for (int o = 16; o; o >>= 1) {
        s1 += __shfl_down_sync(0xffffffffu, s1, o);
        s2 += __shfl_down_sync(0xffffffffu, s2, o);
    }
    if (lane == 0) { g_fsrc[i] = s1 + ab[0]; g_fdst[i] = s2; }
}

// ---------------- kernel 3: softmax stats + bit-pack (coalesced int4) -------
__global__ __launch_bounds__(256) void k_prep(const int* __restrict__ adj) {
    const int i = blockIdx.x, t = threadIdx.x;
    const float fs = g_fsrc[i];
    const int4* arow = (const int4*)(adj + (size_t)i * N);
    const float4* fdp = (const float4*)g_fdst;

    float fdv[16];
    unsigned bits = 0;
#pragma unroll
    for (int u = 0; u < 4; u++) {
        int idx = u * 256 + t;              // coalesced: stride-1 across warp
        int4 a = arow[idx];
        float4 f = fdp[idx];
        fdv[u * 4 + 0] = f.x; fdv[u * 4 + 1] = f.y;
        fdv[u * 4 + 2] = f.z; fdv[u * 4 + 3] = f.w;
        unsigned nib = 0;
        if (a.x > 0) nib |= 1u;
        if (a.y > 0) nib |= 2u;
        if (a.z > 0) nib |= 4u;
        if (a.w > 0) nib |= 8u;
        bits |= nib << (u * 4);
        // pack 8 threads' nibbles into one 32-bit mask word
        unsigned v = nib << ((t & 7) * 4);
        v |= __shfl_xor_sync(0xffffffffu, v, 1);
        v |= __shfl_xor_sync(0xffffffffu, v, 2);
        v |= __shfl_xor_sync(0xffffffffu, v, 4);
        if ((t & 7) == 0) g_mask[(size_t)i * 128 + u * 32 + (t >> 3)] = v;
    }

    float mx = -3.4e38f;
#pragma unroll
    for (int v = 0; v < 16; v++)
        if ((bits >> v) & 1u) mx = fmaxf(mx, fdv[v]);
#pragma unroll
    for (int o = 16; o; o >>= 1) mx = fmaxf(mx, __shfl_xor_sync(0xffffffffu, mx, o));
    __shared__ float redm[8];
    __shared__ float reds[8];
    if ((t & 31) == 0) redm[t >> 5] = mx;
    __syncthreads();
    float mxall = redm[0];
#pragma unroll
    for (int w = 1; w < 8; w++) mxall = fmaxf(mxall, redm[w]);
    float xm = fs + mxall;
    float mi = fmaxf(xm, ALPHA * xm);

    float s = 0.f;
#pragma unroll
    for (int v = 0; v < 16; v++)
        if ((bits >> v) & 1u) {
            float x = fs + fdv[v];
            s += __expf(fmaxf(x, ALPHA * x) - mi);
        }
#pragma unroll
    for (int o = 16; o; o >>= 1) s += __shfl_xor_sync(0xffffffffu, s, o);
    if ((t & 31) == 0) reds[t >> 5] = s;
    __syncthreads();
    if (t == 0) {
        float stot = 0.f;
#pragma unroll
        for (int w = 0; w < 8; w++) stot += reds[w];
        g_mi[i] = mi;
        g_rz[i] = (stot > 0.f) ? (1.f / stot) : 0.f;
    }
}

// ---------------- kernel 4: HMMA attention GEMM, fp16 2-pass ----------------
// 1024 thr / 32 warps; warp grid mw = warp>>3 (16-row quarters), nw = warp&7.
// smem: fd 8KB | mask 16KB | 2 stages x 75KB {A 9216 | B_HI 33792 | B_LO 33792}
#define SM_FD 0
#define SM_MASK 8192
#define SM_STG0 24576
#define A_OFF 0
#define B_HI 9216
#define B_LO 43008
#define STG 76800
#define SMEM_AT (SM_STG0 + 2 * STG)  // 178176

__global__ __launch_bounds__(1024, 1) void k_attn_h() {
    extern __shared__ char smem[];
    const uint32_t sbase = smem_u32(smem);
    float* fd_s = (float*)(smem + SM_FD);
    unsigned* mask_s = (unsigned*)(smem + SM_MASK);
    const int t = threadIdx.x;
    const int lane = t & 31, warp = t >> 5;
    const int mw = warp >> 3, nw = warp & 7;
    const int i0 = blockIdx.x * 64;
    const int js = blockIdx.y;
    const int jorg = js * KCTA;

    // per-thread A-gen constants: thread generates weights for row i = t>>4
    const int gi = i0 + (t >> 4);
    const float fsi = g_fsrc[gi];
    const float mii = g_mi[gi];
    const float rzi = g_rz[gi];

    // preload fd (2048 floats) + mask (64 rows x 64 words = 4096)
    if (t < 512) *(float4*)(fd_s + t * 4) = *(const float4*)(g_fdst + jorg + t * 4);
#pragma unroll
    for (int u = 0; u < 4; u++) {
        int idx = t + 1024 * u;
        mask_s[idx] = g_mask[(size_t)(i0 + (idx >> 6)) * 128 + js * 64 + (idx & 63)];
    }
    __syncthreads();

    auto fill_B = [&](int c2, uint32_t stg_s) {
        size_t jg = (size_t)jorg + (size_t)c2 * 64;
#pragma unroll
        for (int u = 0; u < 2; u++) {
            int idx = t + 1024 * u;
            int j = idx >> 5, dq = idx & 31;
            uint32_t dst = stg_s + B_HI + j * 528 + dq * 16;
            size_t src = (jg + j) * FOUT + dq * 8;
            CP_ASYNC16(dst, (const void*)(g_wh_hi + src));
            CP_ASYNC16(dst + (B_LO - B_HI), (const void*)(g_wh_lo + src));
        }
    };
    // each thread: row t>>4 (0..63), j-quad t&15 (4 j values), fp16 single part
    auto fill_A = [&](int c2, char* stgp) {
        const int row = t >> 4, quad = t & 15;
        unsigned w = mask_s[row * 64 + c2 * 2 + (quad >> 3)] >> ((quad & 7) * 4);
        const float* fdp = fd_s + c2 * 64 + quad * 4;
        uint32_t hv[2];
#pragma unroll
        for (int v = 0; v < 4; v += 2) {
            float e0 = 0.f, e1 = 0.f;
            if ((w >> v) & 1u) {
                float x = fsi + fdp[v];
                e0 = __expf(fmaxf(x, ALPHA * x) - mii) * rzi;
            }
            if ((w >> (v + 1)) & 1u) {
                float x = fsi + fdp[v + 1];
                e1 = __expf(fmaxf(x, ALPHA * x) - mii) * rzi;
            }
            __half2 h2 = __floats2half2_rn(e0, e1);
            hv[v >> 1] = *(uint32_t*)&h2;
        }
        *(uint2*)(stgp + A_OFF + row * 144 + quad * 8) = make_uint2(hv[0], hv[1]);
    };

    float acc[4][4];
#pragma unroll
    for (int b = 0; b < 4; b++)
#pragma unroll
        for (int c = 0; c < 4; c++) acc[b][c] = 0.f;

    // ldmatrix per-thread base offsets
    const uint32_t a_off = (mw * 16 + (lane & 15)) * 144 + (lane >> 4) * 16;
    const uint32_t b_off = (lane & 15) * 528 + (nw * 32 + (lane >> 4) * 8) * 2;

    // prolog: fill chunk 0 into stage 0
    fill_B(0, sbase + SM_STG0);
    CP_COMMIT();
    fill_A(0, smem + SM_STG0);
    CP_WAIT0();
    __syncthreads();

#pragma unroll 1
    for (int c = 0; c < NCHUNK; c++) {
        const int s = c & 1;
        const uint32_t stg = SM_STG0 + (uint32_t)s * STG;
        const uint32_t stg2 = SM_STG0 + (uint32_t)(s ^ 1) * STG;
        const uint32_t Aa = sbase + stg + A_OFF;
        const uint32_t Bh = sbase + stg + B_HI;
        const uint32_t Bl = sbase + stg + B_LO;

        if (c + 1 < NCHUNK) { fill_B(c + 1, sbase + stg2); CP_COMMIT(); }

#pragma unroll
        for (int kk = 0; kk < 4; kk++) {
            uint32_t ah[4], bh[2][4], bl[2][4];
            const uint32_t ao = a_off + kk * 32;
            const uint32_t bo = b_off + kk * 8448;
            ldm_x4(ah, Aa + ao);
#pragma unroll
            for (int seg = 0; seg < 2; seg++) {
                ldm_x4_t(bh[seg], Bh + bo + seg * 32);
                ldm_x4_t(bl[seg], Bl + bo + seg * 32);
            }
#pragma unroll
            for (int nb = 0; nb < 4; nb++) {
                const uint32_t* bfh = &bh[nb >> 1][(nb & 1) * 2];
                const uint32_t* bfl = &bl[nb >> 1][(nb & 1) * 2];
                mma_f16(acc[nb], ah, bfh);  // a * b_hi
                mma_f16(acc[nb], ah, bfl);  // a * b_lo
            }
            if (kk == 0 && c + 1 < NCHUNK) fill_A(c + 1, smem + stg2);
        }

        CP_WAIT0();
        __syncthreads();
    }

    // epilogue: write partials
    float* base = g_part + (size_t)js * ((size_t)N * FOUT);
    {
        int ir = i0 + mw * 16 + (lane >> 2);
#pragma unroll
        for (int nb = 0; nb < 4; nb++) {
            int d = nw * 32 + nb * 8 + (lane & 3) * 2;
            *(float2*)(base + (size_t)ir * FOUT + d) =
                make_float2(acc[nb][0], acc[nb][1]);
            *(float2*)(base + (size_t)(ir + 8) * FOUT + d) =
                make_float2(acc[nb][2], acc[nb][3]);
        }
    }
}

// ---------------- kernel 5: combine partials + elu ----------------
__global__ __launch_bounds__(256) void k_comb(float* __restrict__ out) {
    const size_t idx = ((size_t)blockIdx.x * 256 + threadIdx.x) * 4;
    const size_t stride = (size_t)N * FOUT;
    float4 a = *(const float4*)(g_part + idx);
    float4 b = *(const float4*)(g_part + stride + idx);
    float4 o;
    o.x = a.x + b.x; o.y = a.y + b.y; o.z = a.z + b.z; o.w = a.w + b.w;
    o.x = o.x > 0.f ? o.x : (__expf(o.x) - 1.f);
    o.y = o.y > 0.f ? o.y : (__expf(o.y) - 1.f);
    o.z = o.z > 0.f ? o.z : (__expf(o.z) - 1.f);
    o.w = o.w > 0.f ? o.w : (__expf(o.w) - 1.f);
    *(float4*)(out + idx) = o;
}

// ---------------- launch ----------------
extern "C" void kernel_launch(void* const* d_in, const int* in_sizes, int n_in,
                              void* d_out, int out_size) {
    const int* adj = (const int*)d_in[0];
    const float* h = (const float*)d_in[1];
    const float* Wm = (const float*)d_in[2];
    const float* b = (const float*)d_in[3];
    const float* a1 = (const float*)d_in[4];
    const float* a2 = (const float*)d_in[5];
    const float* ab = (const float*)d_in[6];
    float* out = (float*)d_out;

    static bool attr_set = false;
    if (!attr_set) {
        cudaFuncSetAttribute(k_attn_h, cudaFuncAttributeMaxDynamicSharedMemorySize, SMEM_AT);
        attr_set = true;
    }

    k_gemm_wh<<<dim3(N / 64, FOUT / 64), 256>>>(h, Wm, b);
    k_fsd<<<N / 8, 256>>>(a1, a2, ab);
    k_prep<<<N, 256>>>(adj);
    k_attn_h<<<dim3(N / 64, JSPLIT), 1024, SMEM_AT>>>();
    k_comb<<<(N * FOUT) / 1024, 256>>>(out);
}

// round 9
// speedup vs baseline: 1.4053x; 1.2639x over previous
#include <cuda_runtime.h>
#include <cuda_bf16.h>
#include <cuda_fp16.h>
#include <cstdint>

#define N 4096
#define FIN 512
#define FOUT 256
#define ALPHA 0.2f
#define JSPLIT 2
#define KCTA (N / JSPLIT)   // 2048
#define NCHUNK (KCTA / 64)  // 32

// ---------------- device scratch ----------------
__device__ float g_wh[N * FOUT];
__device__ float g_fsrc[N];
__device__ float g_fdst[N];
__device__ float g_mi[N];
__device__ float g_rz[N];
__device__ unsigned g_mask[N * (N / 32)];                    // 2 MB
__device__ __align__(16) __half g_wh_h[N * FOUT];            // 2 MB [j][d] fp16
__device__ __align__(16) float g_part[(size_t)JSPLIT * N * FOUT];  // 8 MB

// ---------------- base-ISA PTX helpers ----------------
__device__ __forceinline__ uint32_t smem_u32(const void* p) {
    uint32_t a;
    asm("{ .reg .u64 t; cvta.to.shared.u64 t, %1; cvt.u32.u64 %0, t; }" : "=r"(a) : "l"(p));
    return a;
}
__device__ __forceinline__ void ldm_x4(uint32_t* r, uint32_t addr) {
    asm volatile("ldmatrix.sync.aligned.m8n8.x4.shared.b16 {%0,%1,%2,%3}, [%4];"
                 : "=r"(r[0]), "=r"(r[1]), "=r"(r[2]), "=r"(r[3]) : "r"(addr));
}
__device__ __forceinline__ void ldm_x4_t(uint32_t* r, uint32_t addr) {
    asm volatile("ldmatrix.sync.aligned.m8n8.x4.trans.shared.b16 {%0,%1,%2,%3}, [%4];"
                 : "=r"(r[0]), "=r"(r[1]), "=r"(r[2]), "=r"(r[3]) : "r"(addr));
}
__device__ __forceinline__ void mma_f16(float* c, const uint32_t* a, const uint32_t* b) {
    asm volatile(
        "mma.sync.aligned.m16n8k16.row.col.f32.f16.f16.f32 "
        "{%0,%1,%2,%3}, {%4,%5,%6,%7}, {%8,%9}, {%0,%1,%2,%3};"
        : "+f"(c[0]), "+f"(c[1]), "+f"(c[2]), "+f"(c[3])
        : "r"(a[0]), "r"(a[1]), "r"(a[2]), "r"(a[3]), "r"(b[0]), "r"(b[1]));
}
#define CP_ASYNC16(dst, src) \
    asm volatile("cp.async.cg.shared.global [%0], [%1], 16;" :: "r"(dst), "l"(src))
#define CP_COMMIT() asm volatile("cp.async.commit_group;" ::: "memory")
#define CP_WAIT0() asm volatile("cp.async.wait_group 0;" ::: "memory")

// ---------------- f32x2 helpers ----------------
__device__ __forceinline__ unsigned long long pk(float lo, float hi) {
    unsigned long long r;
    asm("mov.b64 %0, {%1,%2};" : "=l"(r) : "f"(lo), "f"(hi));
    return r;
}
__device__ __forceinline__ unsigned long long f2fma(unsigned long long a,
                                                    unsigned long long b,
                                                    unsigned long long c) {
    unsigned long long d;
    asm("fma.rn.f32x2 %0, %1, %2, %3;" : "=l"(d) : "l"(a), "l"(b), "l"(c));
    return d;
}
__device__ __forceinline__ float lof(unsigned long long v) { return __uint_as_float((unsigned)v); }
__device__ __forceinline__ float hif(unsigned long long v) { return __uint_as_float((unsigned)(v >> 32)); }

// ---------------- kernel 1: wh = h @ W + b, plus fp16 cast ------------------
__global__ __launch_bounds__(256) void k_gemm_wh(const float* __restrict__ h,
                                                 const float* __restrict__ Wm,
                                                 const float* __restrict__ bias) {
    __shared__ float As[64][33];
    __shared__ float Bs[32][64];
    const int t = threadIdx.x;
    const int m0 = blockIdx.x * 64, n0 = blockIdx.y * 64;
    const int tx = t & 15, ty = t >> 4;
    unsigned long long acc2[4][2];
#pragma unroll
    for (int i = 0; i < 4; i++) { acc2[i][0] = 0ull; acc2[i][1] = 0ull; }
    for (int k0 = 0; k0 < FIN; k0 += 32) {
#pragma unroll
        for (int u = 0; u < 2; u++) {
            int idx = t + u * 256, r = idx >> 3, c = (idx & 7) * 4;
            float4 v = *(const float4*)(h + (size_t)(m0 + r) * FIN + k0 + c);
            As[r][c] = v.x; As[r][c + 1] = v.y; As[r][c + 2] = v.z; As[r][c + 3] = v.w;
        }
#pragma unroll
        for (int u = 0; u < 2; u++) {
            int idx = t + u * 256, r = idx >> 4, c = (idx & 15) * 4;
            *(float4*)(&Bs[r][c]) = *(const float4*)(Wm + (size_t)(k0 + r) * FOUT + n0 + c);
        }
        __syncthreads();
#pragma unroll
        for (int k = 0; k < 32; k++) {
            double2 bd = *(const double2*)(&Bs[k][tx * 4]);
            unsigned long long b01 = __double_as_longlong(bd.x);
            unsigned long long b23 = __double_as_longlong(bd.y);
#pragma unroll
            for (int i = 0; i < 4; i++) {
                float a = As[ty * 4 + i][k];
                unsigned long long ap = pk(a, a);
                acc2[i][0] = f2fma(ap, b01, acc2[i][0]);
                acc2[i][1] = f2fma(ap, b23, acc2[i][1]);
            }
        }
        __syncthreads();
    }
    const int n = n0 + tx * 4;
    float4 bv = *(const float4*)(bias + n);
#pragma unroll
    for (int i = 0; i < 4; i++) {
        float4 o;
        o.x = lof(acc2[i][0]) + bv.x; o.y = hif(acc2[i][0]) + bv.y;
        o.z = lof(acc2[i][1]) + bv.z; o.w = hif(acc2[i][1]) + bv.w;
        size_t gi = (size_t)(m0 + ty * 4 + i) * FOUT + n;
        *(float4*)(g_wh + gi) = o;
        __half2 ha = __floats2half2_rn(o.x, o.y);
        __half2 hb = __floats2half2_rn(o.z, o.w);
        *(uint2*)(g_wh_h + gi) = make_uint2(*(unsigned*)&ha, *(unsigned*)&hb);
    }
}

// ---------------- kernel 2: f_src / f_dst ----------------
__global__ __launch_bounds__(256) void k_fsd(const float* __restrict__ a1,
                                             const float* __restrict__ a2,
                                             const float* __restrict__ ab) {
    const int warp = threadIdx.x >> 5, lane = threadIdx.x & 31;
    const int i = blockIdx.x * 8 + warp;
    const float4* row = (const float4*)(g_wh + (size_t)i * FOUT);
    const float4* A1 = (const float4*)a1;
    const float4* A2 = (const float4*)a2;
    float s1 = 0.f, s2 = 0.f;
#pragma unroll
    for (int u = 0; u < 2; u++) {
        float4 v = row[lane + u * 32], x = A1[lane + u * 32], y = A2[lane + u * 32];
        s1 += v.x * x.x + v.y * x.y + v.z * x.z + v.w * x.w;
        s2 += v.x * y.x + v.y * y.y + v.z * y.z + v.w * y.w;
    }
#pragma unroll
    for (int o = 16; o; o >>= 1) {
        s1 += __shfl_down_sync(0xffffffffu, s1, o);
        s2 += __shfl_down_sync(0xffffffffu, s2, o);
    }
    if (lane == 0) { g_fsrc[i] = s1 + ab[0]; g_fdst[i] = s2; }
}

// ---------------- kernel 3: softmax stats + bit-pack (coalesced int4) -------
__global__ __launch_bounds__(256) void k_prep(const int* __restrict__ adj) {
    const int i = blockIdx.x, t = threadIdx.x;
    const float fs = g_fsrc[i];
    const int4* arow = (const int4*)(adj + (size_t)i * N);
    const float4* fdp = (const float4*)g_fdst;

    float fdv[16];
    unsigned bits = 0;
#pragma unroll
    for (int u = 0; u < 4; u++) {
        int idx = u * 256 + t;              // coalesced: stride-1 across warp
        int4 a = arow[idx];
        float4 f = fdp[idx];
        fdv[u * 4 + 0] = f.x; fdv[u * 4 + 1] = f.y;
        fdv[u * 4 + 2] = f.z; fdv[u * 4 + 3] = f.w;
        unsigned nib = 0;
        if (a.x > 0) nib |= 1u;
        if (a.y > 0) nib |= 2u;
        if (a.z > 0) nib |= 4u;
        if (a.w > 0) nib |= 8u;
        bits |= nib << (u * 4);
        unsigned v = nib << ((t & 7) * 4);
        v |= __shfl_xor_sync(0xffffffffu, v, 1);
        v |= __shfl_xor_sync(0xffffffffu, v, 2);
        v |= __shfl_xor_sync(0xffffffffu, v, 4);
        if ((t & 7) == 0) g_mask[(size_t)i * 128 + u * 32 + (t >> 3)] = v;
    }

    float mx = -3.4e38f;
#pragma unroll
    for (int v = 0; v < 16; v++)
        if ((bits >> v) & 1u) mx = fmaxf(mx, fdv[v]);
#pragma unroll
    for (int o = 16; o; o >>= 1) mx = fmaxf(mx, __shfl_xor_sync(0xffffffffu, mx, o));
    __shared__ float redm[8];
    __shared__ float reds[8];
    if ((t & 31) == 0) redm[t >> 5] = mx;
    __syncthreads();
    float mxall = redm[0];
#pragma unroll
    for (int w = 1; w < 8; w++) mxall = fmaxf(mxall, redm[w]);
    float xm = fs + mxall;
    float mi = fmaxf(xm, ALPHA * xm);

    float s = 0.f;
#pragma unroll
    for (int v = 0; v < 16; v++)
        if ((bits >> v) & 1u) {
            float x = fs + fdv[v];
            s += __expf(fmaxf(x, ALPHA * x) - mi);
        }
#pragma unroll
    for (int o = 16; o; o >>= 1) s += __shfl_xor_sync(0xffffffffu, s, o);
    if ((t & 31) == 0) reds[t >> 5] = s;
    __syncthreads();
    if (t == 0) {
        float stot = 0.f;
#pragma unroll
        for (int w = 0; w < 8; w++) stot += reds[w];
        g_mi[i] = mi;
        g_rz[i] = (stot > 0.f) ? (1.f / stot) : 0.f;
    }
}

// ---------------- kernel 4: HMMA attention GEMM, fp16 single-pass -----------
// 1024 thr / 32 warps; warp grid mw = warp>>3 (16-row quarters), nw = warp&7.
// smem: fd 8KB | mask 16KB | 2 stages x 42KB {A 9216 | B 33792}
#define SM_FD 0
#define SM_MASK 8192
#define SM_STG0 24576
#define A_OFF 0
#define B_OFF 9216
#define STG 43008
#define SMEM_AT (SM_STG0 + 2 * STG)  // 110592

__global__ __launch_bounds__(1024, 1) void k_attn_h() {
    extern __shared__ char smem[];
    const uint32_t sbase = smem_u32(smem);
    float* fd_s = (float*)(smem + SM_FD);
    unsigned* mask_s = (unsigned*)(smem + SM_MASK);
    const int t = threadIdx.x;
    const int lane = t & 31, warp = t >> 5;
    const int mw = warp >> 3, nw = warp & 7;
    const int i0 = blockIdx.x * 64;
    const int js = blockIdx.y;
    const int jorg = js * KCTA;

    // per-thread A-gen constants: thread generates weights for row i = t>>4
    const int gi = i0 + (t >> 4);
    const float fsi = g_fsrc[gi];
    const float mii = g_mi[gi];
    const float rzi = g_rz[gi];

    // preload fd (2048 floats) + mask (64 rows x 64 words = 4096)
    if (t < 512) *(float4*)(fd_s + t * 4) = *(const float4*)(g_fdst + jorg + t * 4);
#pragma unroll
    for (int u = 0; u < 4; u++) {
        int idx = t + 1024 * u;
        mask_s[idx] = g_mask[(size_t)(i0 + (idx >> 6)) * 128 + js * 64 + (idx & 63)];
    }
    __syncthreads();

    auto fill_B = [&](int c2, uint32_t stg_s) {
        size_t jg = (size_t)jorg + (size_t)c2 * 64;
#pragma unroll
        for (int u = 0; u < 2; u++) {
            int idx = t + 1024 * u;
            int j = idx >> 5, dq = idx & 31;
            uint32_t dst = stg_s + B_OFF + j * 528 + dq * 16;
            size_t src = (jg + j) * FOUT + dq * 8;
            CP_ASYNC16(dst, (const void*)(g_wh_h + src));
        }
    };
    // each thread: row t>>4 (0..63), j-quad t&15 (4 j values), fp16
    auto fill_A = [&](int c2, char* stgp) {
        const int row = t >> 4, quad = t & 15;
        unsigned w = mask_s[row * 64 + c2 * 2 + (quad >> 3)] >> ((quad & 7) * 4);
        const float* fdp = fd_s + c2 * 64 + quad * 4;
        uint32_t hv[2];
#pragma unroll
        for (int v = 0; v < 4; v += 2) {
            float e0 = 0.f, e1 = 0.f;
            if ((w >> v) & 1u) {
                float x = fsi + fdp[v];
                e0 = __expf(fmaxf(x, ALPHA * x) - mii) * rzi;
            }
            if ((w >> (v + 1)) & 1u) {
                float x = fsi + fdp[v + 1];
                e1 = __expf(fmaxf(x, ALPHA * x) - mii) * rzi;
            }
            __half2 h2 = __floats2half2_rn(e0, e1);
            hv[v >> 1] = *(uint32_t*)&h2;
        }
        *(uint2*)(stgp + A_OFF + row * 144 + quad * 8) = make_uint2(hv[0], hv[1]);
    };

    float acc[4][4];
#pragma unroll
    for (int b = 0; b < 4; b++)
#pragma unroll
        for (int c = 0; c < 4; c++) acc[b][c] = 0.f;

    // ldmatrix per-thread base offsets
    const uint32_t a_off = (mw * 16 + (lane & 15)) * 144 + (lane >> 4) * 16;
    const uint32_t b_off = (lane & 15) * 528 + (nw * 32 + (lane >> 4) * 8) * 2;

    // prolog: fill chunk 0 into stage 0
    fill_B(0, sbase + SM_STG0);
    CP_COMMIT();
    fill_A(0, smem + SM_STG0);
    CP_WAIT0();
    __syncthreads();

#pragma unroll 1
    for (int c = 0; c < NCHUNK; c++) {
        const int s = c & 1;
        const uint32_t stg = SM_STG0 + (uint32_t)s * STG;
        const uint32_t stg2 = SM_STG0 + (uint32_t)(s ^ 1) * STG;
        const uint32_t Aa = sbase + stg + A_OFF;
        const uint32_t Bb = sbase + stg + B_OFF;

        if (c + 1 < NCHUNK) { fill_B(c + 1, sbase + stg2); CP_COMMIT(); }

#pragma unroll
        for (int kk = 0; kk < 4; kk++) {
            uint32_t ah[4], bh[2][4];
            const uint32_t ao = a_off + kk * 32;
            const uint32_t bo = b_off + kk * 8448;
            ldm_x4(ah, Aa + ao);
#pragma unroll
            for (int seg = 0; seg < 2; seg++)
                ldm_x4_t(bh[seg], Bb + bo + seg * 32);
#pragma unroll
            for (int nb = 0; nb < 4; nb++) {
                const uint32_t* bf = &bh[nb >> 1][(nb & 1) * 2];
                mma_f16(acc[nb], ah, bf);
            }
            if (kk == 0 && c + 1 < NCHUNK) fill_A(c + 1, smem + stg2);
        }

        CP_WAIT0();
        __syncthreads();
    }

    // epilogue: write partials
    float* base = g_part + (size_t)js * ((size_t)N * FOUT);
    {
        int ir = i0 + mw * 16 + (lane >> 2);
#pragma unroll
        for (int nb = 0; nb < 4; nb++) {
            int d = nw * 32 + nb * 8 + (lane & 3) * 2;
            *(float2*)(base + (size_t)ir * FOUT + d) =
                make_float2(acc[nb][0], acc[nb][1]);
            *(float2*)(base + (size_t)(ir + 8) * FOUT + d) =
                make_float2(acc[nb][2], acc[nb][3]);
        }
    }
}

// ---------------- kernel 5: combine partials + elu ----------------
__global__ __launch_bounds__(256) void k_comb(float* __restrict__ out) {
    const size_t idx = ((size_t)blockIdx.x * 256 + threadIdx.x) * 4;
    const size_t stride = (size_t)N * FOUT;
    float4 a = *(const float4*)(g_part + idx);
    float4 b = *(const float4*)(g_part + stride + idx);
    float4 o;
    o.x = a.x + b.x; o.y = a.y + b.y; o.z = a.z + b.z; o.w = a.w + b.w;
    o.x = o.x > 0.f ? o.x : (__expf(o.x) - 1.f);
    o.y = o.y > 0.f ? o.y : (__expf(o.y) - 1.f);
    o.z = o.z > 0.f ? o.z : (__expf(o.z) - 1.f);
    o.w = o.w > 0.f ? o.w : (__expf(o.w) - 1.f);
    *(float4*)(out + idx) = o;
}

// ---------------- launch ----------------
extern "C" void kernel_launch(void* const* d_in, const int* in_sizes, int n_in,
                              void* d_out, int out_size) {
    const int* adj = (const int*)d_in[0];
    const float* h = (const float*)d_in[1];
    const float* Wm = (const float*)d_in[2];
    const float* b = (const float*)d_in[3];
    const float* a1 = (const float*)d_in[4];
    const float* a2 = (const float*)d_in[5];
    const float* ab = (const float*)d_in[6];
    float* out = (float*)d_out;

    static bool attr_set = false;
    if (!attr_set) {
        cudaFuncSetAttribute(k_attn_h, cudaFuncAttributeMaxDynamicSharedMemorySize, SMEM_AT);
        attr_set = true;
    }

    k_gemm_wh<<<dim3(N / 64, FOUT / 64), 256>>>(h, Wm, b);
    k_fsd<<<N / 8, 256>>>(a1, a2, ab);
    k_prep<<<N, 256>>>(adj);
    k_attn_h<<<dim3(N / 64, JSPLIT), 1024, SMEM_AT>>>();
    k_comb<<<(N * FOUT) / 1024, 256>>>(out);
}

// round 10
// speedup vs baseline: 1.5329x; 1.0908x over previous
#include <cuda_runtime.h>
#include <cuda_bf16.h>
#include <cuda_fp16.h>
#include <cstdint>

#define N 4096
#define FIN 512
#define FOUT 256
#define ALPHA 0.2f
#define JSPLIT 4
#define KCTA (N / JSPLIT)   // 1024
#define NCHUNK (KCTA / 64)  // 16

// ---------------- device scratch ----------------
__device__ float g_wh[N * FOUT];
__device__ float g_fsrc[N];
__device__ float g_fdst[N];
__device__ float g_mi[N];
__device__ float g_rz[N];
__device__ unsigned g_mask[N * (N / 32)];                    // 2 MB
__device__ __align__(16) __half g_wh_h[N * FOUT];            // 2 MB [j][d] fp16
__device__ __align__(16) float g_part[(size_t)JSPLIT * N * FOUT];  // 16 MB

// ---------------- base-ISA PTX helpers ----------------
__device__ __forceinline__ uint32_t smem_u32(const void* p) {
    uint32_t a;
    asm("{ .reg .u64 t; cvta.to.shared.u64 t, %1; cvt.u32.u64 %0, t; }" : "=r"(a) : "l"(p));
    return a;
}
__device__ __forceinline__ void ldm_x4(uint32_t* r, uint32_t addr) {
    asm volatile("ldmatrix.sync.aligned.m8n8.x4.shared.b16 {%0,%1,%2,%3}, [%4];"
                 : "=r"(r[0]), "=r"(r[1]), "=r"(r[2]), "=r"(r[3]) : "r"(addr));
}
__device__ __forceinline__ void ldm_x4_t(uint32_t* r, uint32_t addr) {
    asm volatile("ldmatrix.sync.aligned.m8n8.x4.trans.shared.b16 {%0,%1,%2,%3}, [%4];"
                 : "=r"(r[0]), "=r"(r[1]), "=r"(r[2]), "=r"(r[3]) : "r"(addr));
}
__device__ __forceinline__ void mma_f16(float* c, const uint32_t* a, const uint32_t* b) {
    asm volatile(
        "mma.sync.aligned.m16n8k16.row.col.f32.f16.f16.f32 "
        "{%0,%1,%2,%3}, {%4,%5,%6,%7}, {%8,%9}, {%0,%1,%2,%3};"
        : "+f"(c[0]), "+f"(c[1]), "+f"(c[2]), "+f"(c[3])
        : "r"(a[0]), "r"(a[1]), "r"(a[2]), "r"(a[3]), "r"(b[0]), "r"(b[1]));
}
#define CP_ASYNC16(dst, src) \
    asm volatile("cp.async.cg.shared.global [%0], [%1], 16;" :: "r"(dst), "l"(src))
#define CP_COMMIT() asm volatile("cp.async.commit_group;" ::: "memory")
#define CP_WAIT0() asm volatile("cp.async.wait_group 0;" ::: "memory")

// ---------------- f32x2 helpers ----------------
__device__ __forceinline__ unsigned long long pk(float lo, float hi) {
    unsigned long long r;
    asm("mov.b64 %0, {%1,%2};" : "=l"(r) : "f"(lo), "f"(hi));
    return r;
}
__device__ __forceinline__ unsigned long long f2fma(unsigned long long a,
                                                    unsigned long long b,
                                                    unsigned long long c) {
    unsigned long long d;
    asm("fma.rn.f32x2 %0, %1, %2, %3;" : "=l"(d) : "l"(a), "l"(b), "l"(c));
    return d;
}
__device__ __forceinline__ float lof(unsigned long long v) { return __uint_as_float((unsigned)v); }
__device__ __forceinline__ float hif(unsigned long long v) { return __uint_as_float((unsigned)(v >> 32)); }

// ---------------- kernel 1: wh = h @ W + b, plus fp16 cast ------------------
__global__ __launch_bounds__(256) void k_gemm_wh(const float* __restrict__ h,
                                                 const float* __restrict__ Wm,
                                                 const float* __restrict__ bias) {
    __shared__ float As[64][33];
    __shared__ float Bs[32][64];
    const int t = threadIdx.x;
    const int m0 = blockIdx.x * 64, n0 = blockIdx.y * 64;
    const int tx = t & 15, ty = t >> 4;
    unsigned long long acc2[4][2];
#pragma unroll
    for (int i = 0; i < 4; i++) { acc2[i][0] = 0ull; acc2[i][1] = 0ull; }
    for (int k0 = 0; k0 < FIN; k0 += 32) {
#pragma unroll
        for (int u = 0; u < 2; u++) {
            int idx = t + u * 256, r = idx >> 3, c = (idx & 7) * 4;
            float4 v = *(const float4*)(h + (size_t)(m0 + r) * FIN + k0 + c);
            As[r][c] = v.x; As[r][c + 1] = v.y; As[r][c + 2] = v.z; As[r][c + 3] = v.w;
        }
#pragma unroll
        for (int u = 0; u < 2; u++) {
            int idx = t + u * 256, r = idx >> 4, c = (idx & 15) * 4;
            *(float4*)(&Bs[r][c]) = *(const float4*)(Wm + (size_t)(k0 + r) * FOUT + n0 + c);
        }
        __syncthreads();
#pragma unroll
        for (int k = 0; k < 32; k++) {
            double2 bd = *(const double2*)(&Bs[k][tx * 4]);
            unsigned long long b01 = __double_as_longlong(bd.x);
            unsigned long long b23 = __double_as_longlong(bd.y);
#pragma unroll
            for (int i = 0; i < 4; i++) {
                float a = As[ty * 4 + i][k];
                unsigned long long ap = pk(a, a);
                acc2[i][0] = f2fma(ap, b01, acc2[i][0]);
                acc2[i][1] = f2fma(ap, b23, acc2[i][1]);
            }
        }
        __syncthreads();
    }
    const int n = n0 + tx * 4;
    float4 bv = *(const float4*)(bias + n);
#pragma unroll
    for (int i = 0; i < 4; i++) {
        float4 o;
        o.x = lof(acc2[i][0]) + bv.x; o.y = hif(acc2[i][0]) + bv.y;
        o.z = lof(acc2[i][1]) + bv.z; o.w = hif(acc2[i][1]) + bv.w;
        size_t gi = (size_t)(m0 + ty * 4 + i) * FOUT + n;
        *(float4*)(g_wh + gi) = o;
        __half2 ha = __floats2half2_rn(o.x, o.y);
        __half2 hb = __floats2half2_rn(o.z, o.w);
        *(uint2*)(g_wh_h + gi) = make_uint2(*(unsigned*)&ha, *(unsigned*)&hb);
    }
}

// ---------------- kernel 2: f_src / f_dst ----------------
__global__ __launch_bounds__(256) void k_fsd(const float* __restrict__ a1,
                                             const float* __restrict__ a2,
                                             const float* __restrict__ ab) {
    const int warp = threadIdx.x >> 5, lane = threadIdx.x & 31;
    const int i = blockIdx.x * 8 + warp;
    const float4* row = (const float4*)(g_wh + (size_t)i * FOUT);
    const float4* A1 = (const float4*)a1;
    const float4* A2 = (const float4*)a2;
    float s1 = 0.f, s2 = 0.f;
#pragma unroll
    for (int u = 0; u < 2; u++) {
        float4 v = row[lane + u * 32], x = A1[lane + u * 32], y = A2[lane + u * 32];
        s1 += v.x * x.x + v.y * x.y + v.z * x.z + v.w * x.w;
        s2 += v.x * y.x + v.y * y.y + v.z * y.z + v.w * y.w;
    }
#pragma unroll
    for (int o = 16; o; o >>= 1) {
        s1 += __shfl_down_sync(0xffffffffu, s1, o);
        s2 += __shfl_down_sync(0xffffffffu, s2, o);
    }
    if (lane == 0) { g_fsrc[i] = s1 + ab[0]; g_fdst[i] = s2; }
}

// ---------------- kernel 3: softmax stats + bit-pack (coalesced int4) -------
__global__ __launch_bounds__(256) void k_prep(const int* __restrict__ adj) {
    const int i = blockIdx.x, t = threadIdx.x;
    const float fs = g_fsrc[i];
    const int4* arow = (const int4*)(adj + (size_t)i * N);
    const float4* fdp = (const float4*)g_fdst;

    float fdv[16];
    unsigned bits = 0;
#pragma unroll
    for (int u = 0; u < 4; u++) {
        int idx = u * 256 + t;              // coalesced: stride-1 across warp
        int4 a = arow[idx];
        float4 f = fdp[idx];
        fdv[u * 4 + 0] = f.x; fdv[u * 4 + 1] = f.y;
        fdv[u * 4 + 2] = f.z; fdv[u * 4 + 3] = f.w;
        unsigned nib = 0;
        if (a.x > 0) nib |= 1u;
        if (a.y > 0) nib |= 2u;
        if (a.z > 0) nib |= 4u;
        if (a.w > 0) nib |= 8u;
        bits |= nib << (u * 4);
        unsigned v = nib << ((t & 7) * 4);
        v |= __shfl_xor_sync(0xffffffffu, v, 1);
        v |= __shfl_xor_sync(0xffffffffu, v, 2);
        v |= __shfl_xor_sync(0xffffffffu, v, 4);
        if ((t & 7) == 0) g_mask[(size_t)i * 128 + u * 32 + (t >> 3)] = v;
    }

    float mx = -3.4e38f;
#pragma unroll
    for (int v = 0; v < 16; v++)
        if ((bits >> v) & 1u) mx = fmaxf(mx, fdv[v]);
#pragma unroll
    for (int o = 16; o; o >>= 1) mx = fmaxf(mx, __shfl_xor_sync(0xffffffffu, mx, o));
    __shared__ float redm[8];
    __shared__ float reds[8];
    if ((t & 31) == 0) redm[t >> 5] = mx;
    __syncthreads();
    float mxall = redm[0];
#pragma unroll
    for (int w = 1; w < 8; w++) mxall = fmaxf(mxall, redm[w]);
    float xm = fs + mxall;
    float mi = fmaxf(xm, ALPHA * xm);

    float s = 0.f;
#pragma unroll
    for (int v = 0; v < 16; v++)
        if ((bits >> v) & 1u) {
            float x = fs + fdv[v];
            s += __expf(fmaxf(x, ALPHA * x) - mi);
        }
#pragma unroll
    for (int o = 16; o; o >>= 1) s += __shfl_xor_sync(0xffffffffu, s, o);
    if ((t & 31) == 0) reds[t >> 5] = s;
    __syncthreads();
    if (t == 0) {
        float stot = 0.f;
#pragma unroll
        for (int w = 0; w < 8; w++) stot += reds[w];
        g_mi[i] = mi;
        g_rz[i] = (stot > 0.f) ? (1.f / stot) : 0.f;
    }
}

// ---------------- kernel 4: HMMA attention GEMM, Mw=32 Nw=32 ----------------
// CTA tile M=128, N=256, K=1024 (16 chunks of 64). 1024 thr / 32 warps.
// warp grid: mw = warp>>3 (four 32-row groups, 2 m-tiles each), nw = warp&7.
// smem: fd 4KB | mask 16KB | 2 stages x 51KB {A 128x144B | B 64x528B}
#define SM_FD 0
#define SM_MASK 4096
#define SM_STG0 20480
#define A_OFF 0
#define B_OFF 18432
#define STG 52224
#define SMEM_AT (SM_STG0 + 2 * STG)  // 124928

__global__ __launch_bounds__(1024, 1) void k_attn_h() {
    extern __shared__ char smem[];
    const uint32_t sbase = smem_u32(smem);
    float* fd_s = (float*)(smem + SM_FD);
    unsigned* mask_s = (unsigned*)(smem + SM_MASK);
    const int t = threadIdx.x;
    const int lane = t & 31, warp = t >> 5;
    const int mw = warp >> 3, nw = warp & 7;
    const int i0 = blockIdx.x * 128;
    const int js = blockIdx.y;
    const int jorg = js * KCTA;

    // per-thread A-gen constants: thread generates weights for row i = t>>3
    const int gi = i0 + (t >> 3);
    const float fsi = g_fsrc[gi];
    const float mii = g_mi[gi];
    const float rzi = g_rz[gi];

    // preload fd (1024 floats) + mask (128 rows x 32 words = 4096)
    if (t < 256) *(float4*)(fd_s + t * 4) = *(const float4*)(g_fdst + jorg + t * 4);
#pragma unroll
    for (int u = 0; u < 4; u++) {
        int idx = t + 1024 * u;
        mask_s[idx] = g_mask[(size_t)(i0 + (idx >> 5)) * 128 + js * 32 + (idx & 31)];
    }
    __syncthreads();

    auto fill_B = [&](int c2, uint32_t stg_s) {
        size_t jg = (size_t)jorg + (size_t)c2 * 64;
#pragma unroll
        for (int u = 0; u < 2; u++) {
            int idx = t + 1024 * u;
            int j = idx >> 5, dq = idx & 31;
            uint32_t dst = stg_s + B_OFF + j * 528 + dq * 16;
            size_t src = (jg + j) * FOUT + dq * 8;
            CP_ASYNC16(dst, (const void*)(g_wh_h + src));
        }
    };
    // each thread: row t>>3 (0..127), j-octet t&7 (8 j values), fp16
    auto fill_A = [&](int c2, char* stgp) {
        const int row = t >> 3, oct = t & 7;
        unsigned w = mask_s[row * 32 + c2 * 2 + (oct >> 2)] >> ((oct & 3) * 8);
        const float* fdp = fd_s + c2 * 64 + oct * 8;
        uint32_t hv[4];
#pragma unroll
        for (int v = 0; v < 8; v += 2) {
            float e0 = 0.f, e1 = 0.f;
            if ((w >> v) & 1u) {
                float x = fsi + fdp[v];
                e0 = __expf(fmaxf(x, ALPHA * x) - mii) * rzi;
            }
            if ((w >> (v + 1)) & 1u) {
                float x = fsi + fdp[v + 1];
                e1 = __expf(fmaxf(x, ALPHA * x) - mii) * rzi;
            }
            __half2 h2 = __floats2half2_rn(e0, e1);
            hv[v >> 1] = *(uint32_t*)&h2;
        }
        *(uint4*)(stgp + A_OFF + row * 144 + oct * 16) =
            make_uint4(hv[0], hv[1], hv[2], hv[3]);
    };

    float acc[2][4][4];
#pragma unroll
    for (int a = 0; a < 2; a++)
#pragma unroll
        for (int b = 0; b < 4; b++)
#pragma unroll
            for (int c = 0; c < 4; c++) acc[a][b][c] = 0.f;

    // ldmatrix per-thread base offsets
    const uint32_t a_off = (mw * 32 + (lane & 15)) * 144 + (lane >> 4) * 16;
    const uint32_t b_off = (lane & 15) * 528 + (nw * 32 + (lane >> 4) * 8) * 2;

    // prolog: fill chunk 0 into stage 0
    fill_B(0, sbase + SM_STG0);
    CP_COMMIT();
    fill_A(0, smem + SM_STG0);
    CP_WAIT0();
    __syncthreads();

#pragma unroll 1
    for (int c = 0; c < NCHUNK; c++) {
        const int s = c & 1;
        const uint32_t stg = SM_STG0 + (uint32_t)s * STG;
        const uint32_t stg2 = SM_STG0 + (uint32_t)(s ^ 1) * STG;
        const uint32_t Aa = sbase + stg + A_OFF;
        const uint32_t Bb = sbase + stg + B_OFF;

        if (c + 1 < NCHUNK) { fill_B(c + 1, sbase + stg2); CP_COMMIT(); }

#pragma unroll
        for (int kk = 0; kk < 4; kk++) {
            uint32_t bh[2][4];
            const uint32_t ao = a_off + kk * 32;
            const uint32_t bo = b_off + kk * 8448;
#pragma unroll
            for (int seg = 0; seg < 2; seg++)
                ldm_x4_t(bh[seg], Bb + bo + seg * 32);
#pragma unroll
            for (int mt = 0; mt < 2; mt++) {
                uint32_t ah[4];
                ldm_x4(ah, Aa + ao + mt * (16 * 144));
#pragma unroll
                for (int nb = 0; nb < 4; nb++) {
                    const uint32_t* bf = &bh[nb >> 1][(nb & 1) * 2];
                    mma_f16(acc[mt][nb], ah, bf);
                }
            }
            if (kk == 0 && c + 1 < NCHUNK) fill_A(c + 1, smem + stg2);
        }

        CP_WAIT0();
        __syncthreads();
    }

    // epilogue: write partials
    float* base = g_part + (size_t)js * ((size_t)N * FOUT);
#pragma unroll
    for (int mt = 0; mt < 2; mt++) {
        int ir = i0 + mw * 32 + mt * 16 + (lane >> 2);
#pragma unroll
        for (int nb = 0; nb < 4; nb++) {
            int d = nw * 32 + nb * 8 + (lane & 3) * 2;
            *(float2*)(base + (size_t)ir * FOUT + d) =
                make_float2(acc[mt][nb][0], acc[mt][nb][1]);
            *(float2*)(base + (size_t)(ir + 8) * FOUT + d) =
                make_float2(acc[mt][nb][2], acc[mt][nb][3]);
        }
    }
}

// ---------------- kernel 5: combine partials + elu ----------------
__global__ __launch_bounds__(256) void k_comb(float* __restrict__ out) {
    const size_t idx = ((size_t)blockIdx.x * 256 + threadIdx.x) * 4;
    const size_t stride = (size_t)N * FOUT;
    float4 a = *(const float4*)(g_part + idx);
    float4 b = *(const float4*)(g_part + stride + idx);
    float4 c = *(const float4*)(g_part + 2 * stride + idx);
    float4 d = *(const float4*)(g_part + 3 * stride + idx);
    float4 o;
    o.x = (a.x + b.x) + (c.x + d.x);
    o.y = (a.y + b.y) + (c.y + d.y);
    o.z = (a.z + b.z) + (c.z + d.z);
    o.w = (a.w + b.w) + (c.w + d.w);
    o.x = o.x > 0.f ? o.x : (__expf(o.x) - 1.f);
    o.y = o.y > 0.f ? o.y : (__expf(o.y) - 1.f);
    o.z = o.z > 0.f ? o.z : (__expf(o.z) - 1.f);
    o.w = o.w > 0.f ? o.w : (__expf(o.w) - 1.f);
    *(float4*)(out + idx) = o;
}

// ---------------- launch ----------------
extern "C" void kernel_launch(void* const* d_in, const int* in_sizes, int n_in,
                              void* d_out, int out_size) {
    const int* adj = (const int*)d_in[0];
    const float* h = (const float*)d_in[1];
    const float* Wm = (const float*)d_in[2];
    const float* b = (const float*)d_in[3];
    const float* a1 = (const float*)d_in[4];
    const float* a2 = (const float*)d_in[5];
    const float* ab = (const float*)d_in[6];
    float* out = (float*)d_out;

    static bool attr_set = false;
    if (!attr_set) {
        cudaFuncSetAttribute(k_attn_h, cudaFuncAttributeMaxDynamicSharedMemorySize, SMEM_AT);
        attr_set = true;
    }

    k_gemm_wh<<<dim3(N / 64, FOUT / 64), 256>>>(h, Wm, b);
    k_fsd<<<N / 8, 256>>>(a1, a2, ab);
    k_prep<<<N, 256>>>(adj);
    k_attn_h<<<dim3(N / 128, JSPLIT), 1024, SMEM_AT>>>();
    k_comb<<<(N * FOUT) / 1024, 256>>>(out);
}